// round 1
// baseline (speedup 1.0000x reference)
#include <cuda_runtime.h>
#include <math.h>

#define BB 256
#define NN 256
#define DD 136
#define HH 128
#define ROWS (BB*NN)
#define TM 128          // rows per block in MLP kernel
#define NTHREADS 256

// scratch for scores (no cudaMalloc allowed)
__device__ float g_scores[ROWS];

// smem: phase1: Fs[128][136] @0 (17408 f), W1s[136][128] @17408 (17408 f)
//       phase2: h1s[128][128] @0 (16384 f), W2s[128][128] @17408 (16384 f)
//       reduction reuses W region.
#define SMEM_FLOATS (TM*DD + DD*HH)   // 34816 floats = 139264 bytes

__global__ __launch_bounds__(NTHREADS, 1)
void mlp_kernel(const float* __restrict__ feat,
                const float* __restrict__ W1, const float* __restrict__ b1,
                const float* __restrict__ W2, const float* __restrict__ b2,
                const float* __restrict__ W3, const float* __restrict__ b3)
{
    extern __shared__ float smem[];
    float* A  = smem;               // features, then h1
    float* Wb = smem + TM * DD;     // W1, then W2, then reduction buffer

    const int tid = threadIdx.x;
    const int tx  = tid & 15;       // column group (16 groups x 8 cols)
    const int ty  = tid >> 4;       // row group    (16 groups x 8 rows)
    const long row0 = (long)blockIdx.x * TM;

    // ---- cooperative loads: features tile [128][136] and W1 [136][128] ----
    const float* fptr = feat + row0 * DD;
    #pragma unroll 4
    for (int idx = tid * 4; idx < TM * DD; idx += NTHREADS * 4)
        *(float4*)(A + idx) = *(const float4*)(fptr + idx);
    #pragma unroll 4
    for (int idx = tid * 4; idx < DD * HH; idx += NTHREADS * 4)
        *(float4*)(Wb + idx) = *(const float4*)(W1 + idx);

    // per-thread bias preload
    float bias1[8], bias2[8], w3r[8];
    #pragma unroll
    for (int j = 0; j < 8; j++) {
        bias1[j] = __ldg(b1 + tx * 8 + j);
        bias2[j] = __ldg(b2 + tx * 8 + j);
        w3r[j]   = __ldg(W3 + tx * 8 + j);
    }
    const float bias3 = __ldg(b3);

    __syncthreads();

    float acc[8][8];
    #pragma unroll
    for (int i = 0; i < 8; i++)
        #pragma unroll
        for (int j = 0; j < 8; j++) acc[i][j] = 0.f;

    // ---- layer 1: [128 x 136] @ [136 x 128] ----
    #pragma unroll 2
    for (int k = 0; k < DD; k += 4) {
        float a[8][4];
        #pragma unroll
        for (int i = 0; i < 8; i++) {
            float4 v = *(const float4*)(A + (ty * 8 + i) * DD + k);
            a[i][0] = v.x; a[i][1] = v.y; a[i][2] = v.z; a[i][3] = v.w;
        }
        float bb[4][8];
        #pragma unroll
        for (int kk = 0; kk < 4; kk++) {
            float4 v0 = *(const float4*)(Wb + (k + kk) * HH + tx * 8);
            float4 v1 = *(const float4*)(Wb + (k + kk) * HH + tx * 8 + 4);
            bb[kk][0] = v0.x; bb[kk][1] = v0.y; bb[kk][2] = v0.z; bb[kk][3] = v0.w;
            bb[kk][4] = v1.x; bb[kk][5] = v1.y; bb[kk][6] = v1.z; bb[kk][7] = v1.w;
        }
        #pragma unroll
        for (int kk = 0; kk < 4; kk++)
            #pragma unroll
            for (int i = 0; i < 8; i++)
                #pragma unroll
                for (int j = 0; j < 8; j++)
                    acc[i][j] = fmaf(a[i][kk], bb[kk][j], acc[i][j]);
    }

    __syncthreads();   // everyone done reading Fs / W1s

    // bias + relu, write h1 row-major [128][128] into A; load W2 into Wb
    #pragma unroll
    for (int i = 0; i < 8; i++) {
        float4 v0, v1;
        v0.x = fmaxf(acc[i][0] + bias1[0], 0.f);
        v0.y = fmaxf(acc[i][1] + bias1[1], 0.f);
        v0.z = fmaxf(acc[i][2] + bias1[2], 0.f);
        v0.w = fmaxf(acc[i][3] + bias1[3], 0.f);
        v1.x = fmaxf(acc[i][4] + bias1[4], 0.f);
        v1.y = fmaxf(acc[i][5] + bias1[5], 0.f);
        v1.z = fmaxf(acc[i][6] + bias1[6], 0.f);
        v1.w = fmaxf(acc[i][7] + bias1[7], 0.f);
        *(float4*)(A + (ty * 8 + i) * HH + tx * 8)     = v0;
        *(float4*)(A + (ty * 8 + i) * HH + tx * 8 + 4) = v1;
    }
    #pragma unroll 4
    for (int idx = tid * 4; idx < HH * HH; idx += NTHREADS * 4)
        *(float4*)(Wb + idx) = *(const float4*)(W2 + idx);

    __syncthreads();

    #pragma unroll
    for (int i = 0; i < 8; i++)
        #pragma unroll
        for (int j = 0; j < 8; j++) acc[i][j] = 0.f;

    // ---- layer 2: [128 x 128] @ [128 x 128] ----
    #pragma unroll 2
    for (int k = 0; k < HH; k += 4) {
        float a[8][4];
        #pragma unroll
        for (int i = 0; i < 8; i++) {
            float4 v = *(const float4*)(A + (ty * 8 + i) * HH + k);
            a[i][0] = v.x; a[i][1] = v.y; a[i][2] = v.z; a[i][3] = v.w;
        }
        float bb[4][8];
        #pragma unroll
        for (int kk = 0; kk < 4; kk++) {
            float4 v0 = *(const float4*)(Wb + (k + kk) * HH + tx * 8);
            float4 v1 = *(const float4*)(Wb + (k + kk) * HH + tx * 8 + 4);
            bb[kk][0] = v0.x; bb[kk][1] = v0.y; bb[kk][2] = v0.z; bb[kk][3] = v0.w;
            bb[kk][4] = v1.x; bb[kk][5] = v1.y; bb[kk][6] = v1.z; bb[kk][7] = v1.w;
        }
        #pragma unroll
        for (int kk = 0; kk < 4; kk++)
            #pragma unroll
            for (int i = 0; i < 8; i++)
                #pragma unroll
                for (int j = 0; j < 8; j++)
                    acc[i][j] = fmaf(a[i][kk], bb[kk][j], acc[i][j]);
    }

    // ---- layer 3: relu(h2) . W3, partial per thread over its 8 cols ----
    float p[8];
    #pragma unroll
    for (int i = 0; i < 8; i++) {
        float s = 0.f;
        #pragma unroll
        for (int j = 0; j < 8; j++) {
            float v = fmaxf(acc[i][j] + bias2[j], 0.f);
            s = fmaf(v, w3r[j], s);
        }
        p[i] = s;
    }

    __syncthreads();  // layer-2 smem reads done; reuse Wb for reduction
    float* red = Wb;  // [128 rows][16 col-groups]
    #pragma unroll
    for (int i = 0; i < 8; i++)
        red[(ty * 8 + i) * 16 + tx] = p[i];
    __syncthreads();

    if (tid < TM) {
        float s = bias3;
        #pragma unroll
        for (int t = 0; t < 16; t++) s += red[tid * 16 + t];
        g_scores[row0 + tid] = s;
    }
}

// ---- pairwise lambda kernel: one block per batch ----
__global__ __launch_bounds__(NN, 4)
void lambda_kernel(const int* __restrict__ labels, float* __restrict__ out)
{
    __shared__ float es[NN];
    __shared__ float Ls[NN];
    __shared__ float gs[NN];
    __shared__ int   ls[NN];

    const int b = blockIdx.x;
    const int i = threadIdx.x;

    float s  = g_scores[b * NN + i];
    int   li = labels[b * NN + i];
    es[i] = expf(s);
    Ls[i] = log2f(1.0f + s);
    ls[i] = li;
    gs[i] = exp2f((float)li);
    __syncthreads();

    const float ei = es[i];
    const float Li = Ls[i];
    const float gi = gs[i];

    float acc = 0.f;
    #pragma unroll 8
    for (int j = 0; j < NN; j++) {
        int   lj = ls[j];
        float ej = es[j];
        float Lj = Ls[j];
        float gj = gs[j];
        // numerator of sigmoid term: li>lj -> +ei ; li<lj -> -ej ; eq -> 0
        float numer = (li > lj) ? ei : ((li < lj) ? -ej : 0.f);
        float dl = 1.0f + fmaxf(Li, Lj);
        // dndcg = |(gi-gj)/dl|  (abs of whole quotient, matching reference)
        float w = 0.5f * fabsf(__fdividef(gi - gj, dl));
        acc += __fdividef(numer, ei + ej) * w;
    }
    out[b * NN + i] = acc;
}

extern "C" void kernel_launch(void* const* d_in, const int* in_sizes, int n_in,
                              void* d_out, int out_size)
{
    const float* feat = (const float*)d_in[0];   // (256,256,136) f32
    const int*   labels = (const int*)d_in[1];   // (256,256) i32
    const float* W1 = (const float*)d_in[2];     // (136,128)
    const float* b1 = (const float*)d_in[3];     // (128,)
    const float* W2 = (const float*)d_in[4];     // (128,128)
    const float* b2 = (const float*)d_in[5];     // (128,)
    const float* W3 = (const float*)d_in[6];     // (128,1)
    const float* b3 = (const float*)d_in[7];     // (1,)
    float* out = (float*)d_out;

    static bool attr_set = false;
    if (!attr_set) {
        cudaFuncSetAttribute(mlp_kernel, cudaFuncAttributeMaxDynamicSharedMemorySize,
                             SMEM_FLOATS * (int)sizeof(float));
        attr_set = true;
    }

    mlp_kernel<<<ROWS / TM, NTHREADS, SMEM_FLOATS * sizeof(float)>>>(
        feat, W1, b1, W2, b2, W3, b3);
    lambda_kernel<<<BB, NN>>>(labels, out);
}

// round 2
// speedup vs baseline: 1.0681x; 1.0681x over previous
#include <cuda_runtime.h>
#include <math.h>

#define BB 256
#define NN 256
#define DD 136
#define HH 128
#define ROWS (BB*NN)
#define TM 128          // rows per block in MLP kernel
#define NTHREADS 256

typedef unsigned long long u64;

// packed fp32x2 FMA (sm_100+): d.lo = a.lo*b.lo + c.lo ; d.hi = a.hi*b.hi + c.hi
#define FMA2(d, a, b, c) \
    asm("fma.rn.f32x2 %0, %1, %2, %3;" : "=l"(d) : "l"(a), "l"(b), "l"(c))
#define PACK2(d, x) \
    asm("mov.b64 %0, {%1, %1};" : "=l"(d) : "r"(__float_as_uint(x)))

__device__ __forceinline__ float2 unpack2(u64 v) {
    float2 f;
    asm("mov.b64 {%0, %1}, %2;" : "=f"(f.x), "=f"(f.y) : "l"(v));
    return f;
}

// scratch for scores (no cudaMalloc allowed)
__device__ float g_scores[ROWS];

// smem: phase1: Fs[128][136] @0, W1s[136][128] @17408
//       phase2: h1s[128][128] @0, W2s[128][128] @17408; reduction reuses W region.
#define SMEM_FLOATS (TM*DD + DD*HH)   // 34816 floats = 139264 bytes

__global__ __launch_bounds__(NTHREADS, 1)
void mlp_kernel(const float* __restrict__ feat,
                const float* __restrict__ W1, const float* __restrict__ b1,
                const float* __restrict__ W2, const float* __restrict__ b2,
                const float* __restrict__ W3, const float* __restrict__ b3)
{
    extern __shared__ float smem[];
    float* A  = smem;               // features, then h1
    float* Wb = smem + TM * DD;     // W1, then W2, then reduction buffer

    const int tid = threadIdx.x;
    const int tx  = tid & 15;       // column group (16 groups x 8 cols)
    const int ty  = tid >> 4;       // row group    (16 groups x 8 rows)
    const long row0 = (long)blockIdx.x * TM;

    // ---- cooperative loads: features tile [128][136] and W1 [136][128] ----
    const float* fptr = feat + row0 * DD;
    #pragma unroll 4
    for (int idx = tid * 4; idx < TM * DD; idx += NTHREADS * 4)
        *(float4*)(A + idx) = *(const float4*)(fptr + idx);
    #pragma unroll 4
    for (int idx = tid * 4; idx < DD * HH; idx += NTHREADS * 4)
        *(float4*)(Wb + idx) = *(const float4*)(W1 + idx);

    // per-thread bias preload
    float bias1[8], bias2[8], w3r[8];
    #pragma unroll
    for (int j = 0; j < 8; j++) {
        bias1[j] = __ldg(b1 + tx * 8 + j);
        bias2[j] = __ldg(b2 + tx * 8 + j);
        w3r[j]   = __ldg(W3 + tx * 8 + j);
    }
    const float bias3 = __ldg(b3);

    __syncthreads();

    // packed accumulators: acc2[i][p] holds cols (2p, 2p+1) for row i
    u64 acc2[8][4];
    #pragma unroll
    for (int i = 0; i < 8; i++)
        #pragma unroll
        for (int p = 0; p < 4; p++) acc2[i][p] = 0ULL;

    // ---- layer 1: [128 x 136] @ [136 x 128], packed fp32x2 ----
    #pragma unroll 2
    for (int k = 0; k < DD; k += 4) {
        float a[8][4];
        #pragma unroll
        for (int i = 0; i < 8; i++) {
            float4 v = *(const float4*)(A + (ty * 8 + i) * DD + k);
            a[i][0] = v.x; a[i][1] = v.y; a[i][2] = v.z; a[i][3] = v.w;
        }
        u64 b2r[4][4];
        #pragma unroll
        for (int kk = 0; kk < 4; kk++) {
            ulonglong2 p0 = *(const ulonglong2*)(Wb + (k + kk) * HH + tx * 8);
            ulonglong2 p1 = *(const ulonglong2*)(Wb + (k + kk) * HH + tx * 8 + 4);
            b2r[kk][0] = p0.x; b2r[kk][1] = p0.y;
            b2r[kk][2] = p1.x; b2r[kk][3] = p1.y;
        }
        #pragma unroll
        for (int kk = 0; kk < 4; kk++)
            #pragma unroll
            for (int i = 0; i < 8; i++) {
                u64 a2; PACK2(a2, a[i][kk]);
                FMA2(acc2[i][0], a2, b2r[kk][0], acc2[i][0]);
                FMA2(acc2[i][1], a2, b2r[kk][1], acc2[i][1]);
                FMA2(acc2[i][2], a2, b2r[kk][2], acc2[i][2]);
                FMA2(acc2[i][3], a2, b2r[kk][3], acc2[i][3]);
            }
    }

    __syncthreads();   // everyone done reading Fs / W1s

    // bias + relu, write h1 row-major [128][128] into A; load W2 into Wb
    #pragma unroll
    for (int i = 0; i < 8; i++) {
        float r[8];
        #pragma unroll
        for (int p = 0; p < 4; p++) {
            float2 v = unpack2(acc2[i][p]);
            r[2*p]   = fmaxf(v.x + bias1[2*p],   0.f);
            r[2*p+1] = fmaxf(v.y + bias1[2*p+1], 0.f);
        }
        float4 v0 = {r[0], r[1], r[2], r[3]};
        float4 v1 = {r[4], r[5], r[6], r[7]};
        *(float4*)(A + (ty * 8 + i) * HH + tx * 8)     = v0;
        *(float4*)(A + (ty * 8 + i) * HH + tx * 8 + 4) = v1;
    }
    #pragma unroll 4
    for (int idx = tid * 4; idx < HH * HH; idx += NTHREADS * 4)
        *(float4*)(Wb + idx) = *(const float4*)(W2 + idx);

    __syncthreads();

    #pragma unroll
    for (int i = 0; i < 8; i++)
        #pragma unroll
        for (int p = 0; p < 4; p++) acc2[i][p] = 0ULL;

    // ---- layer 2: [128 x 128] @ [128 x 128], packed fp32x2 ----
    #pragma unroll 2
    for (int k = 0; k < HH; k += 4) {
        float a[8][4];
        #pragma unroll
        for (int i = 0; i < 8; i++) {
            float4 v = *(const float4*)(A + (ty * 8 + i) * HH + k);
            a[i][0] = v.x; a[i][1] = v.y; a[i][2] = v.z; a[i][3] = v.w;
        }
        u64 b2r[4][4];
        #pragma unroll
        for (int kk = 0; kk < 4; kk++) {
            ulonglong2 p0 = *(const ulonglong2*)(Wb + (k + kk) * HH + tx * 8);
            ulonglong2 p1 = *(const ulonglong2*)(Wb + (k + kk) * HH + tx * 8 + 4);
            b2r[kk][0] = p0.x; b2r[kk][1] = p0.y;
            b2r[kk][2] = p1.x; b2r[kk][3] = p1.y;
        }
        #pragma unroll
        for (int kk = 0; kk < 4; kk++)
            #pragma unroll
            for (int i = 0; i < 8; i++) {
                u64 a2; PACK2(a2, a[i][kk]);
                FMA2(acc2[i][0], a2, b2r[kk][0], acc2[i][0]);
                FMA2(acc2[i][1], a2, b2r[kk][1], acc2[i][1]);
                FMA2(acc2[i][2], a2, b2r[kk][2], acc2[i][2]);
                FMA2(acc2[i][3], a2, b2r[kk][3], acc2[i][3]);
            }
    }

    // ---- layer 3: relu(h2) . W3, partial per thread over its 8 cols ----
    float p[8];
    #pragma unroll
    for (int i = 0; i < 8; i++) {
        float s = 0.f;
        #pragma unroll
        for (int pp = 0; pp < 4; pp++) {
            float2 v = unpack2(acc2[i][pp]);
            float v0 = fmaxf(v.x + bias2[2*pp],   0.f);
            float v1 = fmaxf(v.y + bias2[2*pp+1], 0.f);
            s = fmaf(v0, w3r[2*pp],   s);
            s = fmaf(v1, w3r[2*pp+1], s);
        }
        p[i] = s;
    }

    __syncthreads();  // layer-2 smem reads done; reuse Wb for reduction
    float* red = Wb;  // [128 rows][16 col-groups]
    #pragma unroll
    for (int i = 0; i < 8; i++)
        red[(ty * 8 + i) * 16 + tx] = p[i];
    __syncthreads();

    if (tid < TM) {
        float s = bias3;
        #pragma unroll
        for (int t = 0; t < 16; t++) s += red[tid * 16 + t];
        g_scores[row0 + tid] = s;
    }
}

// ---- pairwise lambda kernel: one block per batch ----
__global__ __launch_bounds__(NN, 4)
void lambda_kernel(const int* __restrict__ labels, float* __restrict__ out)
{
    __shared__ float es[NN];
    __shared__ float Ls[NN];
    __shared__ float gs[NN];
    __shared__ int   ls[NN];

    const int b = blockIdx.x;
    const int i = threadIdx.x;

    float s  = g_scores[b * NN + i];
    int   li = labels[b * NN + i];
    es[i] = expf(s);
    Ls[i] = log2f(1.0f + s);
    ls[i] = li;
    gs[i] = exp2f((float)li);
    __syncthreads();

    const float ei = es[i];
    const float Li = Ls[i];
    const float gi = gs[i];

    float acc = 0.f;
    #pragma unroll 8
    for (int j = 0; j < NN; j++) {
        int   lj = ls[j];
        float ej = es[j];
        float Lj = Ls[j];
        float gj = gs[j];
        // numerator of sigmoid term: li>lj -> +ei ; li<lj -> -ej ; eq -> 0
        float numer = (li > lj) ? ei : ((li < lj) ? -ej : 0.f);
        float dl = 1.0f + fmaxf(Li, Lj);
        // term = numer/(ei+ej) * 0.5*|(gi-gj)/dl|
        //      = numer * 0.5*|gi-gj| * rcp(|dl|*(ei+ej))   [sign-exact: ei+ej>0]
        float num2  = numer * (0.5f * fabsf(gi - gj));
        float denom = fabsf(dl) * (ei + ej);
        acc += __fdividef(num2, denom);
    }
    out[b * NN + i] = acc;
}

extern "C" void kernel_launch(void* const* d_in, const int* in_sizes, int n_in,
                              void* d_out, int out_size)
{
    const float* feat = (const float*)d_in[0];   // (256,256,136) f32
    const int*   labels = (const int*)d_in[1];   // (256,256) i32
    const float* W1 = (const float*)d_in[2];     // (136,128)
    const float* b1 = (const float*)d_in[3];     // (128,)
    const float* W2 = (const float*)d_in[4];     // (128,128)
    const float* b2 = (const float*)d_in[5];     // (128,)
    const float* W3 = (const float*)d_in[6];     // (128,1)
    const float* b3 = (const float*)d_in[7];     // (1,)
    float* out = (float*)d_out;

    static bool attr_set = false;
    if (!attr_set) {
        cudaFuncSetAttribute(mlp_kernel, cudaFuncAttributeMaxDynamicSharedMemorySize,
                             SMEM_FLOATS * (int)sizeof(float));
        attr_set = true;
    }

    mlp_kernel<<<ROWS / TM, NTHREADS, SMEM_FLOATS * sizeof(float)>>>(
        feat, W1, b1, W2, b2, W3, b3);
    lambda_kernel<<<BB, NN>>>(labels, out);
}

// round 4
// speedup vs baseline: 1.5710x; 1.4709x over previous
#include <cuda_runtime.h>
#include <cuda_bf16.h>
#include <math.h>
#include <stdint.h>

#define BB 256
#define NN 256
#define DD 136
#define HH 128
#define ROWS (BB*NN)

#define K1PAD 152      // layer-1 K stride in bf16 elems (covers K=144 used; 304B rows -> conflict-free ldmatrix)
#define K1USE 144      // 9 ksteps of 16
#define K2PAD 136      // layer-2 K stride (272B rows -> conflict-free)
#define NT    512      // 16 warps

// ---------------- scratch globals ----------------
__device__ float g_scores[ROWS];
__device__ __align__(16) __nv_bfloat16 g_W1h[HH * K1PAD];
__device__ __align__(16) __nv_bfloat16 g_W1l[HH * K1PAD];
__device__ __align__(16) __nv_bfloat16 g_W2h[HH * K2PAD];
__device__ __align__(16) __nv_bfloat16 g_W2l[HH * K2PAD];

// ---------------- smem layout ----------------
#define A_BYTES (128 * K1PAD * 2)          // 38912
#define OFF_AH  0
#define OFF_AL  (A_BYTES)
#define OFF_WH  (2 * A_BYTES)
#define OFF_WL  (3 * A_BYTES)
#define OFF_B1  (4 * A_BYTES)
#define OFF_B2  (OFF_B1 + 512)
#define OFF_W3  (OFF_B2 + 512)
#define OFF_RED (OFF_W3 + 512)
#define SMEM_BYTES (OFF_RED + 1024)        // 158208

__device__ __forceinline__ uint32_t smem_u32(const void* p) {
    uint32_t a;
    asm("{ .reg .u64 t; cvta.to.shared.u64 t, %1; cvt.u32.u64 %0, t; }" : "=r"(a) : "l"(p));
    return a;
}
__device__ __forceinline__ void ldsm_x4(uint32_t* r, uint32_t addr) {
    asm volatile("ldmatrix.sync.aligned.m8n8.x4.shared.b16 {%0,%1,%2,%3}, [%4];"
        : "=r"(r[0]), "=r"(r[1]), "=r"(r[2]), "=r"(r[3]) : "r"(addr));
}
__device__ __forceinline__ void mma16816(float* d, const uint32_t* a, uint32_t b0, uint32_t b1) {
    asm volatile("mma.sync.aligned.m16n8k16.row.col.f32.bf16.bf16.f32 "
        "{%0,%1,%2,%3}, {%4,%5,%6,%7}, {%8,%9}, {%0,%1,%2,%3};"
        : "+f"(d[0]), "+f"(d[1]), "+f"(d[2]), "+f"(d[3])
        : "r"(a[0]), "r"(a[1]), "r"(a[2]), "r"(a[3]), "r"(b0), "r"(b1));
}
__device__ __forceinline__ uint32_t pack_hi(float x, float y) {
    __nv_bfloat16 h0 = __float2bfloat16(x), h1 = __float2bfloat16(y);
    return ((uint32_t)__bfloat16_as_ushort(h1) << 16) | __bfloat16_as_ushort(h0);
}
__device__ __forceinline__ uint32_t pack_lo(float x, float y) {
    __nv_bfloat16 h0 = __float2bfloat16(x), h1 = __float2bfloat16(y);
    __nv_bfloat16 l0 = __float2bfloat16(x - __bfloat162float(h0));
    __nv_bfloat16 l1 = __float2bfloat16(y - __bfloat162float(h1));
    return ((uint32_t)__bfloat16_as_ushort(l1) << 16) | __bfloat16_as_ushort(l0);
}

// ---------------- weight prep: split + transpose to [n][k] ----------------
__global__ void prep_w(const float* __restrict__ W1, const float* __restrict__ W2) {
    int idx = blockIdx.x * 256 + threadIdx.x;
    if (idx < HH * K1PAD) {                 // n-major over W1_t
        int n = idx & 127, k = idx >> 7;    // k in [0,152)
        float v = (k < DD) ? W1[k * HH + n] : 0.f;
        __nv_bfloat16 hi = __float2bfloat16(v);
        __nv_bfloat16 lo = __float2bfloat16(v - __bfloat162float(hi));
        g_W1h[n * K1PAD + k] = hi;
        g_W1l[n * K1PAD + k] = lo;
        return;
    }
    int idx2 = idx - HH * K1PAD;
    if (idx2 < HH * 128) {
        int n = idx2 & 127, k = idx2 >> 7;  // k in [0,128)
        float v = W2[k * HH + n];
        __nv_bfloat16 hi = __float2bfloat16(v);
        __nv_bfloat16 lo = __float2bfloat16(v - __bfloat162float(hi));
        g_W2h[n * K2PAD + k] = hi;
        g_W2l[n * K2PAD + k] = lo;
    }
}

// ---------------- fused MLP, warp-level bf16 MMA ----------------
__global__ __launch_bounds__(NT, 1)
void mlp_mma(const float* __restrict__ feat,
             const float* __restrict__ b1, const float* __restrict__ b2,
             const float* __restrict__ W3, const float* __restrict__ b3)
{
    extern __shared__ char smem[];
    __nv_bfloat16* AH = (__nv_bfloat16*)(smem + OFF_AH);
    __nv_bfloat16* AL = (__nv_bfloat16*)(smem + OFF_AL);
    float* sB1 = (float*)(smem + OFF_B1);
    float* sB2 = (float*)(smem + OFF_B2);
    float* sW3 = (float*)(smem + OFF_W3);
    float* red = (float*)(smem + OFF_RED);

    const int tid  = threadIdx.x;
    const int lane = tid & 31;
    const int wid  = tid >> 5;
    const int m0    = (wid >> 1) * 16;     // 16-row block
    const int nside = (wid & 1) * 64;      // column half
    const long row0 = (long)blockIdx.x * 128;

    const uint32_t uAH = smem_u32(AH);
    const uint32_t uAL = smem_u32(AL);
    const uint32_t uWH = smem_u32(smem + OFF_WH);
    const uint32_t uWL = smem_u32(smem + OFF_WL);

    // ldmatrix address components
    const int a_row = m0 + (lane & 7) + ((lane >> 3) & 1) * 8;
    const int a_kof = (lane >> 4) * 8;
    const int w_rof = (lane & 7) + (lane >> 4) * 8;       // + n0
    const int w_kof = ((lane >> 3) & 1) * 8;

    // ---- stage: biases/W3 ----
    if (tid < 128) { sB1[tid] = b1[tid]; sB2[tid] = b2[tid]; sW3[tid] = W3[tid]; }

    // ---- stage: features -> hi/lo bf16, stride K1PAD, K padded with zeros ----
    {
        const float* fb = feat + row0 * DD;
        for (int i = tid; i < 128 * 76; i += NT) {
            int r = i / 76, p = i - r * 76;        // pair index, k = 2p
            uint32_t hp = 0, lp = 0;
            if (p < 68) {
                float2 v = *(const float2*)(fb + r * DD + 2 * p);
                hp = pack_hi(v.x, v.y);
                lp = pack_lo(v.x, v.y);
            }
            *(uint32_t*)(AH + r * K1PAD + 2 * p) = hp;
            *(uint32_t*)(AL + r * K1PAD + 2 * p) = lp;
        }
    }
    // ---- stage: W1 tiles (already split/transposed/padded) ----
    {
        uint4* dh = (uint4*)(smem + OFF_WH);
        uint4* dl = (uint4*)(smem + OFF_WL);
        const uint4* sh = (const uint4*)g_W1h;
        const uint4* sl = (const uint4*)g_W1l;
        for (int i = tid; i < A_BYTES / 16; i += NT) { dh[i] = sh[i]; dl[i] = sl[i]; }
    }
    __syncthreads();

    float acc[8][4];
    #pragma unroll
    for (int t = 0; t < 8; t++)
        #pragma unroll
        for (int q = 0; q < 4; q++) acc[t][q] = 0.f;

    // ---- layer 1: 9 ksteps, K stride K1PAD ----
    #pragma unroll
    for (int ks = 0; ks < 9; ks++) {
        const int k0 = ks * 16;
        uint32_t ah[4], al[4];
        ldsm_x4(ah, uAH + (a_row * K1PAD + k0 + a_kof) * 2);
        ldsm_x4(al, uAL + (a_row * K1PAD + k0 + a_kof) * 2);
        #pragma unroll
        for (int np = 0; np < 4; np++) {
            const int n0 = nside + np * 16;
            uint32_t wh[4], wl[4];
            ldsm_x4(wh, uWH + ((n0 + w_rof) * K1PAD + k0 + w_kof) * 2);
            ldsm_x4(wl, uWL + ((n0 + w_rof) * K1PAD + k0 + w_kof) * 2);
            mma16816(acc[2*np],   ah, wh[0], wh[1]);
            mma16816(acc[2*np],   ah, wl[0], wl[1]);
            mma16816(acc[2*np],   al, wh[0], wh[1]);
            mma16816(acc[2*np+1], ah, wh[2], wh[3]);
            mma16816(acc[2*np+1], ah, wl[2], wl[3]);
            mma16816(acc[2*np+1], al, wh[2], wh[3]);
        }
    }
    __syncthreads();    // everyone done reading layer-1 tiles

    // ---- epilogue 1: relu(+b1) -> hi/lo bf16 back to A buffers, stride K2PAD ----
    {
        const int rA = m0 + (lane >> 2);
        #pragma unroll
        for (int nt = 0; nt < 8; nt++) {
            const int c = nside + nt * 8 + (lane & 3) * 2;
            float v0 = fmaxf(acc[nt][0] + sB1[c],     0.f);
            float v1 = fmaxf(acc[nt][1] + sB1[c + 1], 0.f);
            float v2 = fmaxf(acc[nt][2] + sB1[c],     0.f);
            float v3 = fmaxf(acc[nt][3] + sB1[c + 1], 0.f);
            *(uint32_t*)(AH + rA * K2PAD + c)       = pack_hi(v0, v1);
            *(uint32_t*)(AL + rA * K2PAD + c)       = pack_lo(v0, v1);
            *(uint32_t*)(AH + (rA + 8) * K2PAD + c) = pack_hi(v2, v3);
            *(uint32_t*)(AL + (rA + 8) * K2PAD + c) = pack_lo(v2, v3);
        }
    }
    // ---- stage: W2 tiles ----
    {
        uint4* dh = (uint4*)(smem + OFF_WH);
        uint4* dl = (uint4*)(smem + OFF_WL);
        const uint4* sh = (const uint4*)g_W2h;
        const uint4* sl = (const uint4*)g_W2l;
        for (int i = tid; i < (128 * K2PAD * 2) / 16; i += NT) { dh[i] = sh[i]; dl[i] = sl[i]; }
    }
    __syncthreads();

    #pragma unroll
    for (int t = 0; t < 8; t++)
        #pragma unroll
        for (int q = 0; q < 4; q++) acc[t][q] = 0.f;

    // ---- layer 2: 8 ksteps, K stride K2PAD ----
    #pragma unroll
    for (int ks = 0; ks < 8; ks++) {
        const int k0 = ks * 16;
        uint32_t ah[4], al[4];
        ldsm_x4(ah, uAH + (a_row * K2PAD + k0 + a_kof) * 2);
        ldsm_x4(al, uAL + (a_row * K2PAD + k0 + a_kof) * 2);
        #pragma unroll
        for (int np = 0; np < 4; np++) {
            const int n0 = nside + np * 16;
            uint32_t wh[4], wl[4];
            ldsm_x4(wh, uWH + ((n0 + w_rof) * K2PAD + k0 + w_kof) * 2);
            ldsm_x4(wl, uWL + ((n0 + w_rof) * K2PAD + k0 + w_kof) * 2);
            mma16816(acc[2*np],   ah, wh[0], wh[1]);
            mma16816(acc[2*np],   ah, wl[0], wl[1]);
            mma16816(acc[2*np],   al, wh[0], wh[1]);
            mma16816(acc[2*np+1], ah, wh[2], wh[3]);
            mma16816(acc[2*np+1], ah, wl[2], wl[3]);
            mma16816(acc[2*np+1], al, wh[2], wh[3]);
        }
    }

    // ---- epilogue 2: relu(+b2) . W3, reduce to scores ----
    {
        float pl = 0.f, ph = 0.f;
        #pragma unroll
        for (int nt = 0; nt < 8; nt++) {
            const int c = nside + nt * 8 + (lane & 3) * 2;
            pl = fmaf(fmaxf(acc[nt][0] + sB2[c],     0.f), sW3[c],     pl);
            pl = fmaf(fmaxf(acc[nt][1] + sB2[c + 1], 0.f), sW3[c + 1], pl);
            ph = fmaf(fmaxf(acc[nt][2] + sB2[c],     0.f), sW3[c],     ph);
            ph = fmaf(fmaxf(acc[nt][3] + sB2[c + 1], 0.f), sW3[c + 1], ph);
        }
        pl += __shfl_xor_sync(0xFFFFFFFF, pl, 1);
        pl += __shfl_xor_sync(0xFFFFFFFF, pl, 2);
        ph += __shfl_xor_sync(0xFFFFFFFF, ph, 1);
        ph += __shfl_xor_sync(0xFFFFFFFF, ph, 2);
        if ((lane & 3) == 0) {
            const int r = m0 + (lane >> 2);
            red[r * 2 + (wid & 1)]       = pl;
            red[(r + 8) * 2 + (wid & 1)] = ph;
        }
    }
    __syncthreads();
    if (tid < 128)
        g_scores[row0 + tid] = red[tid * 2] + red[tid * 2 + 1] + __ldg(b3);
}

// ---------------- pairwise lambda kernel: 2 blocks per batch ----------------
__global__ __launch_bounds__(128, 8)
void lambda_kernel(const int* __restrict__ labels, float* __restrict__ out)
{
    __shared__ float4 elg[NN];     // {exp(s), log2(1+s), 2^label, 0}

    const int bid   = blockIdx.x;        // 0..511
    const int batch = bid >> 1;
    const int half  = bid & 1;
    const int tid   = threadIdx.x;

    for (int j = tid; j < NN; j += 128) {
        float s = g_scores[batch * NN + j];
        int   l = labels[batch * NN + j];
        elg[j] = make_float4(expf(s), log2f(1.0f + s), exp2f((float)l), 0.f);
    }
    __syncthreads();

    const int i = half * 128 + tid;
    const float4 me = elg[i];
    const float ei = me.x, Li = me.y, gi = me.z;

    float acc = 0.f;
    #pragma unroll 8
    for (int j = 0; j < NN; j++) {
        float4 v  = elg[j];
        float sg  = gi - v.z;                      // sign(li-lj) == sign(gi-gj)
        float t   = (sg > 0.f) ? ei : v.x;         // +ei if li>lj, else ej
        float num = sg * t;
        float den = fabsf(1.0f + fmaxf(Li, v.y)) * (ei + v.x);
        acc += __fdividef(num, den);
    }
    out[batch * NN + i] = 0.5f * acc;
}

extern "C" void kernel_launch(void* const* d_in, const int* in_sizes, int n_in,
                              void* d_out, int out_size)
{
    const float* feat   = (const float*)d_in[0];   // (256,256,136) f32
    const int*   labels = (const int*)d_in[1];     // (256,256) i32
    const float* W1 = (const float*)d_in[2];       // (136,128)
    const float* b1 = (const float*)d_in[3];       // (128,)
    const float* W2 = (const float*)d_in[4];       // (128,128)
    const float* b2 = (const float*)d_in[5];       // (128,)
    const float* W3 = (const float*)d_in[6];       // (128,1)
    const float* b3 = (const float*)d_in[7];       // (1,)
    float* out = (float*)d_out;

    static bool attr_set = false;
    if (!attr_set) {
        cudaFuncSetAttribute(mlp_mma, cudaFuncAttributeMaxDynamicSharedMemorySize,
                             (int)SMEM_BYTES);
        attr_set = true;
    }

    prep_w<<<(HH * K1PAD + HH * 128 + 255) / 256, 256>>>(W1, W2);
    mlp_mma<<<ROWS / 128, NT, SMEM_BYTES>>>(feat, b1, b2, W3, b3);
    lambda_kernel<<<2 * BB, 128>>>(labels, out);
}

// round 5
// speedup vs baseline: 1.9617x; 1.2487x over previous
#include <cuda_runtime.h>
#include <cuda_bf16.h>
#include <math.h>
#include <stdint.h>

#define BB 256
#define NN 256
#define DD 136
#define HH 128
#define ROWS (BB*NN)

#define K1PAD 152      // layer-1 K stride (304B rows -> conflict-free ldmatrix)
#define K2PAD 136      // layer-2 K stride (272B rows -> conflict-free)
#define NT    512      // 16 warps

// ---------------- scratch globals ----------------
__device__ float g_scores[ROWS];
__device__ __align__(16) __nv_bfloat16 g_W1h[HH * K1PAD];
__device__ __align__(16) __nv_bfloat16 g_W1l[HH * K1PAD];
__device__ __align__(16) __nv_bfloat16 g_W2h[HH * K2PAD];
__device__ __align__(16) __nv_bfloat16 g_W2l[HH * K2PAD];

// ---------------- smem layout (everything staged once) ----------------
#define A_BYTES  (128 * K1PAD * 2)          // 38912
#define W2_BYTES (128 * K2PAD * 2)          // 34816
#define OFF_AH   0
#define OFF_AL   (A_BYTES)                  // 38912
#define OFF_W1H  (2 * A_BYTES)              // 77824
#define OFF_W1L  (3 * A_BYTES)              // 116736
#define OFF_W2H  (4 * A_BYTES)              // 155648
#define OFF_W2L  (OFF_W2H + W2_BYTES)       // 190464
#define OFF_B1   (OFF_W2L + W2_BYTES)       // 225280
#define OFF_B2   (OFF_B1 + 512)
#define OFF_W3   (OFF_B2 + 512)
#define OFF_RED  (OFF_W3 + 512)
#define SMEM_BYTES (OFF_RED + 1024)         // 227840

__device__ __forceinline__ uint32_t smem_u32(const void* p) {
    uint32_t a;
    asm("{ .reg .u64 t; cvta.to.shared.u64 t, %1; cvt.u32.u64 %0, t; }" : "=r"(a) : "l"(p));
    return a;
}
__device__ __forceinline__ void cp_async16(uint32_t dst, const void* src) {
    asm volatile("cp.async.cg.shared.global [%0], [%1], 16;" :: "r"(dst), "l"(src));
}
#define CP_COMMIT() asm volatile("cp.async.commit_group;" ::: "memory")
#define CP_WAIT0()  asm volatile("cp.async.wait_group 0;" ::: "memory")

__device__ __forceinline__ void ldsm_x4(uint32_t* r, uint32_t addr) {
    asm volatile("ldmatrix.sync.aligned.m8n8.x4.shared.b16 {%0,%1,%2,%3}, [%4];"
        : "=r"(r[0]), "=r"(r[1]), "=r"(r[2]), "=r"(r[3]) : "r"(addr));
}
__device__ __forceinline__ void mma16816(float* d, const uint32_t* a, uint32_t b0, uint32_t b1) {
    asm volatile("mma.sync.aligned.m16n8k16.row.col.f32.bf16.bf16.f32 "
        "{%0,%1,%2,%3}, {%4,%5,%6,%7}, {%8,%9}, {%0,%1,%2,%3};"
        : "+f"(d[0]), "+f"(d[1]), "+f"(d[2]), "+f"(d[3])
        : "r"(a[0]), "r"(a[1]), "r"(a[2]), "r"(a[3]), "r"(b0), "r"(b1));
}
__device__ __forceinline__ uint32_t pack_hi(float x, float y) {
    __nv_bfloat16 h0 = __float2bfloat16(x), h1 = __float2bfloat16(y);
    return ((uint32_t)__bfloat16_as_ushort(h1) << 16) | __bfloat16_as_ushort(h0);
}
__device__ __forceinline__ uint32_t pack_lo(float x, float y) {
    __nv_bfloat16 h0 = __float2bfloat16(x), h1 = __float2bfloat16(y);
    __nv_bfloat16 l0 = __float2bfloat16(x - __bfloat162float(h0));
    __nv_bfloat16 l1 = __float2bfloat16(y - __bfloat162float(h1));
    return ((uint32_t)__bfloat16_as_ushort(l1) << 16) | __bfloat16_as_ushort(l0);
}

// ---------------- weight prep: split + transpose to [n][k] ----------------
__global__ void prep_w(const float* __restrict__ W1, const float* __restrict__ W2) {
    int idx = blockIdx.x * 256 + threadIdx.x;
    if (idx < HH * K1PAD) {
        int n = idx & 127, k = idx >> 7;     // coalesced read of W1[k*128+n]
        float v = (k < DD) ? W1[k * HH + n] : 0.f;
        __nv_bfloat16 hi = __float2bfloat16(v);
        __nv_bfloat16 lo = __float2bfloat16(v - __bfloat162float(hi));
        g_W1h[n * K1PAD + k] = hi;
        g_W1l[n * K1PAD + k] = lo;
        return;
    }
    int idx2 = idx - HH * K1PAD;
    if (idx2 < HH * 128) {
        int n = idx2 & 127, k = idx2 >> 7;
        float v = W2[k * HH + n];
        __nv_bfloat16 hi = __float2bfloat16(v);
        __nv_bfloat16 lo = __float2bfloat16(v - __bfloat162float(hi));
        g_W2h[n * K2PAD + k] = hi;
        g_W2l[n * K2PAD + k] = lo;
    }
}

// ---------------- fused MLP, warp-level bf16 MMA ----------------
__global__ __launch_bounds__(NT, 1)
void mlp_mma(const float* __restrict__ feat,
             const float* __restrict__ b1, const float* __restrict__ b2,
             const float* __restrict__ W3, const float* __restrict__ b3)
{
    extern __shared__ char smem[];
    __nv_bfloat16* AH = (__nv_bfloat16*)(smem + OFF_AH);
    __nv_bfloat16* AL = (__nv_bfloat16*)(smem + OFF_AL);
    float* sB1 = (float*)(smem + OFF_B1);
    float* sB2 = (float*)(smem + OFF_B2);
    float* sW3 = (float*)(smem + OFF_W3);
    float* red = (float*)(smem + OFF_RED);

    const int tid  = threadIdx.x;
    const int lane = tid & 31;
    const int wid  = tid >> 5;
    const int m0    = (wid >> 1) * 16;
    const int nside = (wid & 1) * 64;
    const long row0 = (long)blockIdx.x * 128;

    const uint32_t uAH  = smem_u32(smem + OFF_AH);
    const uint32_t uAL  = smem_u32(smem + OFF_AL);
    const uint32_t uW1H = smem_u32(smem + OFF_W1H);
    const uint32_t uW1L = smem_u32(smem + OFF_W1L);
    const uint32_t uW2H = smem_u32(smem + OFF_W2H);
    const uint32_t uW2L = smem_u32(smem + OFF_W2L);

    // ldmatrix address components
    const int a_row = m0 + (lane & 7) + ((lane >> 3) & 1) * 8;
    const int a_kof = (lane >> 4) * 8;
    const int w_rof = (lane & 7) + (lane >> 4) * 8;
    const int w_kof = ((lane >> 3) & 1) * 8;

    // ---- stage 1: all weight tiles via cp.async (issued first, fully async) ----
    {
        const char* s;
        s = (const char*)g_W1h;
        for (int i = tid; i < A_BYTES / 16; i += NT) cp_async16(uW1H + i * 16, s + i * 16);
        s = (const char*)g_W1l;
        for (int i = tid; i < A_BYTES / 16; i += NT) cp_async16(uW1L + i * 16, s + i * 16);
        s = (const char*)g_W2h;
        for (int i = tid; i < W2_BYTES / 16; i += NT) cp_async16(uW2H + i * 16, s + i * 16);
        s = (const char*)g_W2l;
        for (int i = tid; i < W2_BYTES / 16; i += NT) cp_async16(uW2L + i * 16, s + i * 16);
        CP_COMMIT();
    }

    // ---- stage 2: biases / W3 ----
    if (tid < 128) { sB1[tid] = b1[tid]; sB2[tid] = b2[tid]; sW3[tid] = W3[tid]; }

    // ---- stage 3: features, batched loads then convert/store ----
    {
        const int r  = tid >> 2;        // row 0..127
        const int c4 = tid & 3;         // pair-lane
        const float* fb = feat + row0 * DD + (long)r * DD + 2 * c4;
        float2 v[17];
        #pragma unroll
        for (int it = 0; it < 17; it++) v[it] = *(const float2*)(fb + 8 * it);
        #pragma unroll
        for (int it = 0; it < 17; it++) {
            const int p = c4 + 4 * it;          // 0..67
            *(uint32_t*)(AH + r * K1PAD + 2 * p) = pack_hi(v[it].x, v[it].y);
            *(uint32_t*)(AL + r * K1PAD + 2 * p) = pack_lo(v[it].x, v[it].y);
        }
        // zero pad k = 136..151 (pairs 68..75)
        *(uint32_t*)(AH + r * K1PAD + 2 * (68 + c4)) = 0;
        *(uint32_t*)(AL + r * K1PAD + 2 * (68 + c4)) = 0;
        *(uint32_t*)(AH + r * K1PAD + 2 * (72 + c4)) = 0;
        *(uint32_t*)(AL + r * K1PAD + 2 * (72 + c4)) = 0;
    }
    CP_WAIT0();
    __syncthreads();

    float acc[8][4];
    #pragma unroll
    for (int t = 0; t < 8; t++)
        #pragma unroll
        for (int q = 0; q < 4; q++) acc[t][q] = 0.f;

    // ---- layer 1: 9 ksteps, stride K1PAD ----
    #pragma unroll
    for (int ks = 0; ks < 9; ks++) {
        const int k0 = ks * 16;
        uint32_t ah[4], al[4];
        ldsm_x4(ah, uAH + (a_row * K1PAD + k0 + a_kof) * 2);
        ldsm_x4(al, uAL + (a_row * K1PAD + k0 + a_kof) * 2);
        #pragma unroll
        for (int np = 0; np < 4; np++) {
            const int n0 = nside + np * 16;
            uint32_t wh[4], wl[4];
            ldsm_x4(wh, uW1H + ((n0 + w_rof) * K1PAD + k0 + w_kof) * 2);
            ldsm_x4(wl, uW1L + ((n0 + w_rof) * K1PAD + k0 + w_kof) * 2);
            mma16816(acc[2*np],   ah, wh[0], wh[1]);
            mma16816(acc[2*np],   ah, wl[0], wl[1]);
            mma16816(acc[2*np],   al, wh[0], wh[1]);
            mma16816(acc[2*np+1], ah, wh[2], wh[3]);
            mma16816(acc[2*np+1], ah, wl[2], wl[3]);
            mma16816(acc[2*np+1], al, wh[2], wh[3]);
        }
    }
    __syncthreads();    // all layer-1 A reads complete before h1 overwrite

    // ---- epilogue 1: relu(+b1) -> hi/lo bf16 into A buffers, stride K2PAD ----
    {
        const int rA = m0 + (lane >> 2);
        #pragma unroll
        for (int nt = 0; nt < 8; nt++) {
            const int c = nside + nt * 8 + (lane & 3) * 2;
            float v0 = fmaxf(acc[nt][0] + sB1[c],     0.f);
            float v1 = fmaxf(acc[nt][1] + sB1[c + 1], 0.f);
            float v2 = fmaxf(acc[nt][2] + sB1[c],     0.f);
            float v3 = fmaxf(acc[nt][3] + sB1[c + 1], 0.f);
            *(uint32_t*)(AH + rA * K2PAD + c)       = pack_hi(v0, v1);
            *(uint32_t*)(AL + rA * K2PAD + c)       = pack_lo(v0, v1);
            *(uint32_t*)(AH + (rA + 8) * K2PAD + c) = pack_hi(v2, v3);
            *(uint32_t*)(AL + (rA + 8) * K2PAD + c) = pack_lo(v2, v3);
        }
    }
    __syncthreads();

    #pragma unroll
    for (int t = 0; t < 8; t++)
        #pragma unroll
        for (int q = 0; q < 4; q++) acc[t][q] = 0.f;

    // ---- layer 2: 8 ksteps, stride K2PAD (W2 already resident) ----
    #pragma unroll
    for (int ks = 0; ks < 8; ks++) {
        const int k0 = ks * 16;
        uint32_t ah[4], al[4];
        ldsm_x4(ah, uAH + (a_row * K2PAD + k0 + a_kof) * 2);
        ldsm_x4(al, uAL + (a_row * K2PAD + k0 + a_kof) * 2);
        #pragma unroll
        for (int np = 0; np < 4; np++) {
            const int n0 = nside + np * 16;
            uint32_t wh[4], wl[4];
            ldsm_x4(wh, uW2H + ((n0 + w_rof) * K2PAD + k0 + w_kof) * 2);
            ldsm_x4(wl, uW2L + ((n0 + w_rof) * K2PAD + k0 + w_kof) * 2);
            mma16816(acc[2*np],   ah, wh[0], wh[1]);
            mma16816(acc[2*np],   ah, wl[0], wl[1]);
            mma16816(acc[2*np],   al, wh[0], wh[1]);
            mma16816(acc[2*np+1], ah, wh[2], wh[3]);
            mma16816(acc[2*np+1], ah, wl[2], wl[3]);
            mma16816(acc[2*np+1], al, wh[2], wh[3]);
        }
    }

    // ---- epilogue 2: relu(+b2) . W3, reduce to scores ----
    {
        float pl = 0.f, ph = 0.f;
        #pragma unroll
        for (int nt = 0; nt < 8; nt++) {
            const int c = nside + nt * 8 + (lane & 3) * 2;
            pl = fmaf(fmaxf(acc[nt][0] + sB2[c],     0.f), sW3[c],     pl);
            pl = fmaf(fmaxf(acc[nt][1] + sB2[c + 1], 0.f), sW3[c + 1], pl);
            ph = fmaf(fmaxf(acc[nt][2] + sB2[c],     0.f), sW3[c],     ph);
            ph = fmaf(fmaxf(acc[nt][3] + sB2[c + 1], 0.f), sW3[c + 1], ph);
        }
        pl += __shfl_xor_sync(0xFFFFFFFF, pl, 1);
        pl += __shfl_xor_sync(0xFFFFFFFF, pl, 2);
        ph += __shfl_xor_sync(0xFFFFFFFF, ph, 1);
        ph += __shfl_xor_sync(0xFFFFFFFF, ph, 2);
        if ((lane & 3) == 0) {
            const int r = m0 + (lane >> 2);
            red[r * 2 + (wid & 1)]       = pl;
            red[(r + 8) * 2 + (wid & 1)] = ph;
        }
    }
    __syncthreads();
    if (tid < 128)
        g_scores[row0 + tid] = red[tid * 2] + red[tid * 2 + 1] + __ldg(b3);
}

// ---------------- pairwise lambda kernel: 2 blocks per batch ----------------
__global__ __launch_bounds__(128, 8)
void lambda_kernel(const int* __restrict__ labels, float* __restrict__ out)
{
    __shared__ float4 elg[NN];     // {exp(s), log2(1+s), 2^label, 0}

    const int bid   = blockIdx.x;
    const int batch = bid >> 1;
    const int half  = bid & 1;
    const int tid   = threadIdx.x;

    for (int j = tid; j < NN; j += 128) {
        float s = g_scores[batch * NN + j];
        int   l = labels[batch * NN + j];
        elg[j] = make_float4(expf(s), log2f(1.0f + s), exp2f((float)l), 0.f);
    }
    __syncthreads();

    const int i = half * 128 + tid;
    const float4 me = elg[i];
    const float ei = me.x, Li = me.y, gi = me.z;

    float acc = 0.f;
    #pragma unroll 8
    for (int j = 0; j < NN; j++) {
        float4 v  = elg[j];
        float sg  = gi - v.z;
        float t   = (sg > 0.f) ? ei : v.x;
        float num = sg * t;
        float den = fabsf(1.0f + fmaxf(Li, v.y)) * (ei + v.x);
        acc += __fdividef(num, den);
    }
    out[batch * NN + i] = 0.5f * acc;
}

extern "C" void kernel_launch(void* const* d_in, const int* in_sizes, int n_in,
                              void* d_out, int out_size)
{
    const float* feat   = (const float*)d_in[0];
    const int*   labels = (const int*)d_in[1];
    const float* W1 = (const float*)d_in[2];
    const float* b1 = (const float*)d_in[3];
    const float* W2 = (const float*)d_in[4];
    const float* b2 = (const float*)d_in[5];
    const float* W3 = (const float*)d_in[6];
    const float* b3 = (const float*)d_in[7];
    float* out = (float*)d_out;

    static bool attr_set = false;
    if (!attr_set) {
        cudaFuncSetAttribute(mlp_mma, cudaFuncAttributeMaxDynamicSharedMemorySize,
                             (int)SMEM_BYTES);
        attr_set = true;
    }

    prep_w<<<(HH * K1PAD + HH * 128 + 255) / 256, 256>>>(W1, W2);
    mlp_mma<<<ROWS / 128, NT, SMEM_BYTES>>>(feat, b1, b2, W3, b3);
    lambda_kernel<<<2 * BB, 128>>>(labels, out);
}